// round 4
// baseline (speedup 1.0000x reference)
#include <cuda_runtime.h>

// filtfilt (5-tap butter-style IIR, odd ext padlen=15) over 512 rows, T=32768.
//
// R4: single fused kernel, one row per block; the forward intermediate lives
// entirely in shared memory (131KB row buffer), eliminating 167MB of DRAM
// scratch traffic and the second launch. CH=129 = 1 mod 32 makes compute-order
// row-buffer access conflict-free, so fwd writes results directly (no output
// tile) and bwd reads directly (no input tile).
// Stable filter (max |pole|=0.80): WARM=63 -> state error 0.8^63 ~ 8e-7.
// The reference's per-row scale/descale is a linear no-op and skipped.

#define T_LEN  32768
#define PAD    15
#define TEXT   (T_LEN + 2 * PAD)   // 32798
#define NCH    256                 // chunks per row
#define CH     129                 // NCH*CH = 33024 >= TEXT; CH % 32 == 1
#define WARM   63
#define WIN    (WARM + CH)         // 192
#define TILES  (WIN / 32)          // 6
#define WPR    8                   // warps per row
#define BLOCK  (WPR * 32)          // 256
#define LBUF   32800               // row buffer floats (TEXT padded)
#define SMEM_FLOATS (LBUF + WPR * 32 * 33)
#define SMEM_BYTES  (SMEM_FLOATS * 4)

struct Coef {
    float b0, b1, b2, b3, b4;
    float na1, na2, na3, na4;
};

__device__ __forceinline__ Coef load_coef(const float* __restrict__ bc,
                                          const float* __restrict__ ac) {
    Coef c;
    float inva0 = 1.0f / ac[0];
    c.b0 = bc[0] * inva0; c.b1 = bc[1] * inva0; c.b2 = bc[2] * inva0;
    c.b3 = bc[3] * inva0; c.b4 = bc[4] * inva0;
    c.na1 = -ac[1] * inva0; c.na2 = -ac[2] * inva0;
    c.na3 = -ac[3] * inva0; c.na4 = -ac[4] * inva0;
    return c;
}

// Direct-Form-I step; critical chain is the final fma through y1 (4 cyc).
#define IIR_STEP(xt)                                                   \
    do {                                                               \
        float f = fmaf(c.b0, (xt), fmaf(c.b1, x1,                      \
                  fmaf(c.b2, x2, fmaf(c.b3, x3, c.b4 * x4))));         \
        float s_ = fmaf(c.na2, y2, fmaf(c.na3, y3,                     \
                   fmaf(c.na4, y4, f)));                               \
        float y = fmaf(c.na1, y1, s_);                                 \
        x4 = x3; x3 = x2; x2 = x1; x1 = (xt);                          \
        y4 = y3; y3 = y2; y2 = y1; y1 = y;                             \
    } while (0)

// Odd-extended input at extended index t; 0 outside [0, TEXT).
__device__ __forceinline__ float load_xe_safe(const float* __restrict__ xr, int t) {
    if (t < 0)            return 0.0f;
    if (t < PAD)          return 2.0f * xr[0]         - xr[PAD - t];
    if (t < T_LEN + PAD)  return xr[t - PAD];
    if (t < TEXT)         return 2.0f * xr[T_LEN - 1] - xr[2 * T_LEN + PAD - 2 - t];
    return 0.0f;
}

__global__ void __launch_bounds__(BLOCK)
filt_kernel(const float* __restrict__ x,
            const float* __restrict__ bc,
            const float* __restrict__ ac,
            float* __restrict__ out) {
    extern __shared__ float sm_all[];
    float* rowbuf = sm_all;                         // [LBUF]
    int wir  = threadIdx.x >> 5;
    int lane = threadIdx.x & 31;
    float (*tile)[33] = (float (*)[33])(sm_all + LBUF + wir * (32 * 33));

    int row = blockIdx.x;
    Coef c = load_coef(bc, ac);
    const float* xr   = x   + (size_t)row * T_LEN;
    float*       orow = out + (size_t)row * T_LEN;

    int base = wir * 32 * CH - WARM;                // window start, chunk wir*32
    bool fast = (wir > 0) && (wir < WPR - 1);       // no boundary, no overrun

    // ---------------- forward pass ----------------
    float x1 = 0.f, x2 = 0.f, x3 = 0.f, x4 = 0.f;
    float y1 = 0.f, y2 = 0.f, y3 = 0.f, y4 = 0.f;

    for (int tl = 0; tl < TILES; ++tl) {
        int off = tl * 32;
        // Stage 32x32 input tile (coalesced global loads, transposed).
        if (fast) {
            const float* p = xr + (base - PAD) + off + lane;
            #pragma unroll
            for (int i = 0; i < 32; ++i) tile[i][lane] = p[i * CH];
        } else {
            #pragma unroll 4
            for (int i = 0; i < 32; ++i)
                tile[i][lane] = load_xe_safe(xr, base + i * CH + off + lane);
        }
        __syncwarp();
        // Compute; emit straight into rowbuf (lane stride CH=129 -> 32
        // distinct banks, conflict-free STS).
        int tbase = base + lane * CH + off;
        #pragma unroll
        for (int jb = 0; jb < 32; jb += 8) {
            float v[8];
            #pragma unroll
            for (int k = 0; k < 8; ++k) v[k] = tile[lane][jb + k];
            #pragma unroll
            for (int k = 0; k < 8; ++k) {
                IIR_STEP(v[k]);
                int j = off + jb + k;
                int t = tbase + jb + k;
                if (j >= WARM && t < TEXT) rowbuf[t] = y1;
            }
        }
        __syncwarp();
    }

    __syncthreads();   // whole forward row visible to all warps

    // ---------------- backward pass ----------------
    // u[s] = rowbuf[TEXT-1-s]; emit t = TEXT-1-s in crop [PAD, T+PAD)
    // -> s in [PAD, TEXT-1-PAD]; out index (TEXT-1-PAD) - s.
    x1 = x2 = x3 = x4 = 0.f;
    y1 = y2 = y3 = y4 = 0.f;

    for (int tl = 0; tl < TILES; ++tl) {
        int off = tl * 32;
        int sbase = base + lane * CH + off;
        // Compute directly from rowbuf (lane stride -129 -> conflict-free
        // LDS); results into tile for the coalesced transpose store.
        #pragma unroll
        for (int jb = 0; jb < 32; jb += 8) {
            float v[8];
            if (fast) {
                #pragma unroll
                for (int k = 0; k < 8; ++k)
                    v[k] = rowbuf[TEXT - 1 - (sbase + jb + k)];
            } else {
                #pragma unroll
                for (int k = 0; k < 8; ++k) {
                    int s = sbase + jb + k;
                    v[k] = (s >= 0 && s < TEXT) ? rowbuf[TEXT - 1 - s] : 0.f;
                }
            }
            #pragma unroll
            for (int k = 0; k < 8; ++k) {
                IIR_STEP(v[k]);
                tile[lane][jb + k] = y1;
            }
        }
        __syncwarp();
        // Coalesced output stores (descending-consecutive out indices).
        if (tl >= 2) {
            if (fast) {
                float* q = orow + (TEXT - 1 - PAD) - (base + off + lane);
                #pragma unroll
                for (int i = 0; i < 32; ++i) q[-i * CH] = tile[i][lane];
            } else {
                #pragma unroll 4
                for (int i = 0; i < 32; ++i) {
                    int s = base + i * CH + off + lane;
                    if (s >= PAD && s <= TEXT - 1 - PAD)
                        orow[(TEXT - 1 - PAD) - s] = tile[i][lane];
                }
            }
        } else if (tl == 1) {
            if (lane == 31) {   // only off+lane==63 >= WARM emits
                #pragma unroll 4
                for (int i = 0; i < 32; ++i) {
                    int s = base + i * CH + off + lane;
                    if (s >= PAD && s <= TEXT - 1 - PAD)
                        orow[(TEXT - 1 - PAD) - s] = tile[i][lane];
                }
            }
        }
        __syncwarp();
    }
}

extern "C" void kernel_launch(void* const* d_in, const int* in_sizes, int n_in,
                              void* d_out, int out_size) {
    const float* x  = (const float*)d_in[0];
    const float* bc = (const float*)d_in[1];
    const float* ac = (const float*)d_in[2];
    float* out = (float*)d_out;

    int nrows = in_sizes[0] / T_LEN;  // 512

    cudaFuncSetAttribute(filt_kernel,
                         cudaFuncAttributeMaxDynamicSharedMemorySize,
                         SMEM_BYTES);
    filt_kernel<<<nrows, BLOCK, SMEM_BYTES>>>(x, bc, ac, out);
}

// round 5
// speedup vs baseline: 1.7589x; 1.7589x over previous
#include <cuda_runtime.h>

// filtfilt (5-tap butter-style IIR, odd extension padlen=15) over 512 rows
// of T=32768.
//
// R5: two-kernel global-scratch design (R4's fused-smem version starved
// occupancy and regressed). Doubled chunk parallelism: NCH=512 chunks of
// CH=65, WARM=63 (max |pole|=0.80 -> 0.8^63 ~ 8e-7 state error), WIN=128,
// 4 tiles. Two 256-thread blocks per row -> 8192 warps, ~48 resident/SM.
// Scratch (67MB) fits L2, so bwd reads are mostly L2 hits.
// DF1 recurrence: critical chain is one FMA (4 cyc/sample).
// Reference's per-row scale/descale is a linear no-op, skipped.

#define T_LEN     32768
#define PAD       15
#define TEXT      (T_LEN + 2 * PAD)   // 32798
#define ROWSTRIDE 32800
#define MAXROWS   512
#define NCH       512                 // chunks per row
#define CH        65                  // NCH*CH = 33280 >= TEXT
#define WARM      63
#define WIN       (WARM + CH)         // 128
#define TILES     (WIN / 32)          // 4
#define WPR       8                   // warps per block
#define BLOCK     (WPR * 32)          // 256
#define CPB       (WPR * 32)          // chunks per block = 256
#define BPR       (NCH / CPB)         // blocks per row = 2

__device__ float g_fwd[(size_t)MAXROWS * ROWSTRIDE];

struct Coef {
    float b0, b1, b2, b3, b4;
    float na1, na2, na3, na4;
};

__device__ __forceinline__ Coef load_coef(const float* __restrict__ bc,
                                          const float* __restrict__ ac) {
    Coef c;
    float inva0 = 1.0f / ac[0];
    c.b0 = bc[0] * inva0; c.b1 = bc[1] * inva0; c.b2 = bc[2] * inva0;
    c.b3 = bc[3] * inva0; c.b4 = bc[4] * inva0;
    c.na1 = -ac[1] * inva0; c.na2 = -ac[2] * inva0;
    c.na3 = -ac[3] * inva0; c.na4 = -ac[4] * inva0;
    return c;
}

// Direct-Form-I step; critical chain is the final fma through y1 (4 cyc).
#define IIR_STEP(xt)                                                   \
    do {                                                               \
        float f = fmaf(c.b0, (xt), fmaf(c.b1, x1,                      \
                  fmaf(c.b2, x2, fmaf(c.b3, x3, c.b4 * x4))));         \
        float s_ = fmaf(c.na2, y2, fmaf(c.na3, y3,                     \
                   fmaf(c.na4, y4, f)));                               \
        float y = fmaf(c.na1, y1, s_);                                 \
        x4 = x3; x3 = x2; x2 = x1; x1 = (xt);                          \
        y4 = y3; y3 = y2; y2 = y1; y1 = y;                             \
    } while (0)

__device__ __forceinline__ float load_xe_safe(const float* __restrict__ xr, int t) {
    if (t < 0)            return 0.0f;
    if (t < PAD)          return 2.0f * xr[0]         - xr[PAD - t];
    if (t < T_LEN + PAD)  return xr[t - PAD];
    if (t < TEXT)         return 2.0f * xr[T_LEN - 1] - xr[2 * T_LEN + PAD - 2 - t];
    return 0.0f;
}

__device__ __forceinline__ float load_rev_safe(const float* __restrict__ yr, int s) {
    if (s < 0 || s >= TEXT) return 0.0f;
    return yr[TEXT - 1 - s];
}

__global__ void __launch_bounds__(BLOCK)
fwd_kernel(const float* __restrict__ x,
           const float* __restrict__ bc,
           const float* __restrict__ ac) {
    int wir  = threadIdx.x >> 5;
    int lane = threadIdx.x & 31;
    int row  = blockIdx.x / BPR;
    int half = blockIdx.x - row * BPR;

    Coef c = load_coef(bc, ac);
    const float* xr = x + (size_t)row * T_LEN;
    float*       yr = g_fwd + (size_t)row * ROWSTRIDE;

    __shared__ float tile_s[WPR][32][33];
    float (*sm)[33] = tile_s[wir];

    int c0   = half * CPB + wir * 32;   // first chunk of this warp
    int base = c0 * CH - WARM;
    // fast: window never crosses the odd-extension boundary or TEXT.
    bool fast = (c0 != 0) && (c0 + 32 != NCH);

    float x1 = 0.f, x2 = 0.f, x3 = 0.f, x4 = 0.f;
    float y1 = 0.f, y2 = 0.f, y3 = 0.f, y4 = 0.f;

    #pragma unroll
    for (int tl = 0; tl < TILES; ++tl) {
        int off = tl * 32;
        // Phase 1: coalesced transposed loads.
        if (fast) {
            const float* p = xr + (base - PAD) + off + lane;
            #pragma unroll
            for (int i = 0; i < 32; ++i) sm[i][lane] = p[i * CH];
        } else {
            #pragma unroll 4
            for (int i = 0; i < 32; ++i)
                sm[i][lane] = load_xe_safe(xr, base + i * CH + off + lane);
        }
        __syncwarp();
        // Phase 2: lane advances its chunk 32 steps (8-batched LDS).
        #pragma unroll
        for (int jb = 0; jb < 32; jb += 8) {
            float v[8];
            #pragma unroll
            for (int k = 0; k < 8; ++k) v[k] = sm[lane][jb + k];
            #pragma unroll
            for (int k = 0; k < 8; ++k) {
                IIR_STEP(v[k]);
                sm[lane][jb + k] = y1;
            }
        }
        __syncwarp();
        // Phase 3: coalesced stores of emitted samples (off+lane >= WARM).
        if (tl >= 2) {
            if (fast) {
                float* q = yr + base + off + lane;
                #pragma unroll
                for (int i = 0; i < 32; ++i) q[i * CH] = sm[i][lane];
            } else {
                #pragma unroll 4
                for (int i = 0; i < 32; ++i) {
                    int t = base + i * CH + off + lane;
                    if (t >= 0 && t < TEXT) yr[t] = sm[i][lane];
                }
            }
        } else if (tl == 1) {
            if (lane == 31) {   // off+lane == 63 == WARM
                #pragma unroll 4
                for (int i = 0; i < 32; ++i) {
                    int t = base + i * CH + off + lane;
                    if (t >= 0 && t < TEXT) yr[t] = sm[i][lane];
                }
            }
        }
        __syncwarp();
    }
}

__global__ void __launch_bounds__(BLOCK)
bwd_kernel(const float* __restrict__ bc,
           const float* __restrict__ ac,
           float* __restrict__ out) {
    int wir  = threadIdx.x >> 5;
    int lane = threadIdx.x & 31;
    int row  = blockIdx.x / BPR;
    int half = blockIdx.x - row * BPR;

    Coef c = load_coef(bc, ac);
    const float* yr   = g_fwd + (size_t)row * ROWSTRIDE;
    float*       orow = out   + (size_t)row * T_LEN;

    __shared__ float tile_s[WPR][32][33];
    float (*sm)[33] = tile_s[wir];

    int c0   = half * CPB + wir * 32;
    int base = c0 * CH - WARM;
    bool fast = (c0 != 0) && (c0 + 32 != NCH);

    float x1 = 0.f, x2 = 0.f, x3 = 0.f, x4 = 0.f;
    float y1 = 0.f, y2 = 0.f, y3 = 0.f, y4 = 0.f;

    #pragma unroll
    for (int tl = 0; tl < TILES; ++tl) {
        int off = tl * 32;
        // Phase 1: reversed-time reads (descending-consecutive, coalesced).
        if (fast) {
            const float* p = yr + (TEXT - 1) - (base + off + lane);
            #pragma unroll
            for (int i = 0; i < 32; ++i) sm[i][lane] = p[-i * CH];
        } else {
            #pragma unroll 4
            for (int i = 0; i < 32; ++i)
                sm[i][lane] = load_rev_safe(yr, base + i * CH + off + lane);
        }
        __syncwarp();
        #pragma unroll
        for (int jb = 0; jb < 32; jb += 8) {
            float v[8];
            #pragma unroll
            for (int k = 0; k < 8; ++k) v[k] = sm[lane][jb + k];
            #pragma unroll
            for (int k = 0; k < 8; ++k) {
                IIR_STEP(v[k]);
                sm[lane][jb + k] = y1;
            }
        }
        __syncwarp();
        // Phase 3: out position t = TEXT-1-s in crop [PAD, T+PAD)
        // -> s in [PAD, TEXT-1-PAD]; out idx (TEXT-1-PAD) - s, coalesced.
        if (tl >= 2) {
            if (fast) {
                float* q = orow + (TEXT - 1 - PAD) - (base + off + lane);
                #pragma unroll
                for (int i = 0; i < 32; ++i) q[-i * CH] = sm[i][lane];
            } else {
                #pragma unroll 4
                for (int i = 0; i < 32; ++i) {
                    int s = base + i * CH + off + lane;
                    if (s >= PAD && s <= TEXT - 1 - PAD)
                        orow[(TEXT - 1 - PAD) - s] = sm[i][lane];
                }
            }
        } else if (tl == 1) {
            if (lane == 31) {
                #pragma unroll 4
                for (int i = 0; i < 32; ++i) {
                    int s = base + i * CH + off + lane;
                    if (s >= PAD && s <= TEXT - 1 - PAD)
                        orow[(TEXT - 1 - PAD) - s] = sm[i][lane];
                }
            }
        }
        __syncwarp();
    }
}

extern "C" void kernel_launch(void* const* d_in, const int* in_sizes, int n_in,
                              void* d_out, int out_size) {
    const float* x  = (const float*)d_in[0];
    const float* bc = (const float*)d_in[1];
    const float* ac = (const float*)d_in[2];
    float* out = (float*)d_out;

    int nrows  = in_sizes[0] / T_LEN;   // 512
    int blocks = nrows * BPR;           // 1024

    fwd_kernel<<<blocks, BLOCK>>>(x, bc, ac);
    bwd_kernel<<<blocks, BLOCK>>>(bc, ac, out);
}